// round 2
// baseline (speedup 1.0000x reference)
#include <cuda_runtime.h>
#include <math.h>

#define NN 50000
#define EE 800000
#define DD 256
#define HH 4
#define CC 64
#define OUTC 5
#define FD (HH*OUTC)   // 20
#define NEG 0.2f
#define GN_EPS 1e-5f
#define SM_EPS 1e-16f

// ---------------- scratch (device globals, no allocation) ----------------
__device__ float g_emb[NN*DD];
__device__ float g_xl [NN*DD];
__device__ float g_xr [NN*DD];
__device__ float g_lin[NN*DD];
__device__ float g_agg[NN*DD];
__device__ float g_score[EE*HH];
__device__ float g_m  [NN*HH];
__device__ float g_den[NN*HH];
__device__ float g_colsum[DD];
__device__ float g_colsq [DD];
__device__ float g_mshift[DD];
__device__ float g_rsig  [DD];
__device__ float g_fxl [NN*FD];
__device__ float g_fxr [NN*FD];
__device__ float g_fagg[NN*FD];
__device__ float g_flin[NN*OUTC];

static __device__ __forceinline__ void atomicMaxF(float* addr, float val) {
    int old = __float_as_int(*addr);
    while (__int_as_float(old) < val) {
        int assumed = old;
        old = atomicCAS((int*)addr, assumed, __float_as_int(val));
        if (old == assumed) break;
    }
}

// ---------------- SGEMM: C[M,Nc] = A[M,K] @ B[K,Nc] (+bias) --------------
// 64x64 tile, BK=16, 16x16 threads, 4x4 register blocking.
__global__ void k_sgemm(const float* __restrict__ A, const float* __restrict__ B,
                        const float* __restrict__ bias, float* __restrict__ C,
                        int M, int Nc, int K) {
    __shared__ float As[16][64];
    __shared__ float Bs[16][64];

    const int tx = threadIdx.x, ty = threadIdx.y;
    const int tid = ty * 16 + tx;
    const int rowBase = blockIdx.y * 64;
    const int colBase = blockIdx.x * 64;

    float acc[4][4];
    #pragma unroll
    for (int i = 0; i < 4; ++i)
        #pragma unroll
        for (int j = 0; j < 4; ++j) acc[i][j] = 0.f;

    for (int k0 = 0; k0 < K; k0 += 16) {
        #pragma unroll
        for (int t = 0; t < 4; ++t) {
            int li = tid + t * 256;            // 0..1023
            int mA = li >> 4, kA = li & 15;    // A tile: 64 x 16
            int r = rowBase + mA;
            As[kA][mA] = (r < M) ? A[(size_t)r * K + k0 + kA] : 0.f;
            int kB = li >> 6, nB = li & 63;    // B tile: 16 x 64
            int cB = colBase + nB;
            Bs[kB][nB] = (cB < Nc) ? B[(size_t)(k0 + kB) * Nc + cB] : 0.f;
        }
        __syncthreads();

        #pragma unroll
        for (int k = 0; k < 16; ++k) {
            float a[4], b[4];
            #pragma unroll
            for (int i = 0; i < 4; ++i) a[i] = As[k][ty * 4 + i];
            #pragma unroll
            for (int j = 0; j < 4; ++j) b[j] = Bs[k][tx * 4 + j];
            #pragma unroll
            for (int i = 0; i < 4; ++i)
                #pragma unroll
                for (int j = 0; j < 4; ++j) acc[i][j] += a[i] * b[j];
        }
        __syncthreads();
    }

    #pragma unroll
    for (int i = 0; i < 4; ++i) {
        int r = rowBase + ty * 4 + i;
        if (r >= M) continue;
        #pragma unroll
        for (int j = 0; j < 4; ++j) {
            int c = colBase + tx * 4 + j;
            if (c < Nc) {
                float v = acc[i][j];
                if (bias) v += bias[c];
                C[(size_t)r * Nc + c] = v;
            }
        }
    }
}

// ---------------- init kernels ----------------
__global__ void k_init_layer() {
    int i = blockIdx.x * blockDim.x + threadIdx.x;
    if (i < NN*DD) g_agg[i] = 0.f;
    if (i < NN*HH) { g_m[i] = __int_as_float(0xff800000); g_den[i] = 0.f; }
    if (i < DD) { g_colsum[i] = 0.f; g_colsq[i] = 0.f; }
}

__global__ void k_init_final() {
    int i = blockIdx.x * blockDim.x + threadIdx.x;
    if (i < NN*FD) g_fagg[i] = 0.f;
    if (i < NN*HH) { g_m[i] = __int_as_float(0xff800000); g_den[i] = 0.f; }
}

// ---------------- edge scoring (thread per edge-head) ----------------
template<int C>
__global__ void k_edge_score(const float* __restrict__ xl, const float* __restrict__ xr,
                             const float* __restrict__ att, const int* __restrict__ ei) {
    int idx = blockIdx.x * blockDim.x + threadIdx.x;
    if (idx >= EE * HH) return;
    int e = idx >> 2, h = idx & 3;
    int src = ei[e], dst = ei[EE + e];
    const float* pl = xl + (size_t)src * (HH * C) + h * C;
    const float* pr = xr + (size_t)dst * (HH * C) + h * C;
    const float* pa = att + h * C;
    float s = 0.f;
    #pragma unroll 8
    for (int c = 0; c < C; ++c) {
        float v = pl[c] + pr[c];
        v = v > 0.f ? v : NEG * v;
        s += pa[c] * v;
    }
    g_score[idx] = s;
    atomicMaxF(&g_m[dst * HH + h], s);
}

__global__ void k_edge_exp(const int* __restrict__ ei) {
    int idx = blockIdx.x * blockDim.x + threadIdx.x;
    if (idx >= EE * HH) return;
    int e = idx >> 2, h = idx & 3;
    int dst = ei[EE + e];
    float a = expf(g_score[idx] - g_m[dst * HH + h]);
    g_score[idx] = a;
    atomicAdd(&g_den[dst * HH + h], a);
}

// block (256 thr) per edge: scatter alpha * xl[src] into g_agg[dst]
__global__ void k_edge_agg(const int* __restrict__ ei, const float* __restrict__ xl) {
    int e = blockIdx.x;
    int t = threadIdx.x;
    __shared__ float alpha[HH];
    int src = ei[e], dst = ei[EE + e];
    if (t < HH) alpha[t] = g_score[e * HH + t] / (g_den[dst * HH + t] + SM_EPS);
    __syncthreads();
    float v = alpha[t >> 6] * xl[(size_t)src * DD + t];
    atomicAdd(&g_agg[(size_t)dst * DD + t], v);
}

// final-layer aggregation: 32 threads per edge, 20 features
__global__ void k_edge_agg_f(const int* __restrict__ ei) {
    int e = blockIdx.x;
    int t = threadIdx.x;
    __shared__ float alpha[HH];
    int src = ei[e], dst = ei[EE + e];
    if (t < HH) alpha[t] = g_score[e * HH + t] / (g_den[dst * HH + t] + SM_EPS);
    __syncwarp();
    if (t < FD) {
        atomicAdd(&g_fagg[(size_t)dst * FD + t], alpha[t / OUTC] * g_fxl[(size_t)src * FD + t]);
    }
}

// ---------------- GraphNorm ----------------
__global__ void k_colstats(const float* __restrict__ bconv) {
    int t = threadIdx.x;  // column 0..255
    float bc = bconv[t];
    float s = 0.f, q = 0.f;
    for (int r = blockIdx.x; r < NN; r += gridDim.x) {
        float v = g_agg[(size_t)r * DD + t] + bc;
        s += v; q += v * v;
    }
    atomicAdd(&g_colsum[t], s);
    atomicAdd(&g_colsq[t], q);
}

__global__ void k_finstats(const float* __restrict__ gnw, const float* __restrict__ gnms) {
    int t = threadIdx.x;
    float mean = g_colsum[t] * (1.f / NN);
    float ms = mean * gnms[t];
    float var = g_colsq[t] * (1.f / NN) - 2.f * ms * mean + ms * ms;
    g_mshift[t] = ms;
    g_rsig[t] = gnw[t] * rsqrtf(var + GN_EPS);
}

// normalize + skip + ELU -> g_emb
__global__ void k_fuse(const float* __restrict__ bconv, const float* __restrict__ gnb) {
    int i = blockIdx.x * blockDim.x + threadIdx.x;
    if (i >= NN * DD) return;
    int c = i & (DD - 1);
    float v = g_agg[i] + bconv[c];
    v = (v - g_mshift[c]) * g_rsig[c] + gnb[c] + g_lin[i];
    g_emb[i] = v > 0.f ? v : expm1f(v);
}

// ---------------- final combine + log_softmax ----------------
__global__ void k_final(const float* __restrict__ fbconv, float* __restrict__ out) {
    int n = blockIdx.x * blockDim.x + threadIdx.x;
    if (n >= NN) return;
    float t[OUTC];
    #pragma unroll
    for (int o = 0; o < OUTC; ++o) {
        float s = 0.f;
        #pragma unroll
        for (int h = 0; h < HH; ++h) s += g_fagg[(size_t)n * FD + h * OUTC + o];
        t[o] = 0.25f * s + fbconv[o] + g_flin[(size_t)n * OUTC + o];
    }
    float m = t[0];
    #pragma unroll
    for (int o = 1; o < OUTC; ++o) m = fmaxf(m, t[o]);
    float lse = 0.f;
    #pragma unroll
    for (int o = 0; o < OUTC; ++o) lse += expf(t[o] - m);
    lse = logf(lse);
    #pragma unroll
    for (int o = 0; o < OUTC; ++o) out[(size_t)n * OUTC + o] = t[o] - m - lse;
}

// ---------------- host ----------------
static void sgemm(const float* A, const float* B, const float* bias, float* C,
                  int M, int Nc, int K) {
    dim3 grid((Nc + 63) / 64, (M + 63) / 64);
    dim3 blk(16, 16);
    k_sgemm<<<grid, blk>>>(A, B, bias, C, M, Nc, K);
}

extern "C" void kernel_launch(void* const* d_in, const int* in_sizes, int n_in,
                              void* d_out, int out_size) {
    const float* x      = (const float*)d_in[0];
    const int*   ei     = (const int*)d_in[1];
    const float* Wl     = (const float*)d_in[2];
    const float* Wr     = (const float*)d_in[3];
    const float* att    = (const float*)d_in[4];
    const float* bconv  = (const float*)d_in[5];
    const float* Wlin   = (const float*)d_in[6];
    const float* blin   = (const float*)d_in[7];
    const float* gnw    = (const float*)d_in[8];
    const float* gnb    = (const float*)d_in[9];
    const float* gnms   = (const float*)d_in[10];
    const float* fWl    = (const float*)d_in[11];
    const float* fWr    = (const float*)d_in[12];
    const float* fatt   = (const float*)d_in[13];
    const float* fbconv = (const float*)d_in[14];
    const float* fWlin  = (const float*)d_in[15];
    const float* fblin  = (const float*)d_in[16];
    float* out = (float*)d_out;

    float *p_emb, *p_xl, *p_xr, *p_lin, *p_fxl, *p_fxr, *p_flin;
    cudaGetSymbolAddress((void**)&p_emb,  g_emb);
    cudaGetSymbolAddress((void**)&p_xl,   g_xl);
    cudaGetSymbolAddress((void**)&p_xr,   g_xr);
    cudaGetSymbolAddress((void**)&p_lin,  g_lin);
    cudaGetSymbolAddress((void**)&p_fxl,  g_fxl);
    cudaGetSymbolAddress((void**)&p_fxr,  g_fxr);
    cudaGetSymbolAddress((void**)&p_flin, g_flin);

    const int EH_BLOCKS = (EE * HH + 255) / 256;
    const int ND_BLOCKS = (NN * DD + 255) / 256;

    const float* embp = x;
    for (int i = 0; i < 2; ++i) {
        const size_t wo = (size_t)i * DD * DD;
        sgemm(embp, Wl + wo, nullptr, p_xl, NN, DD, DD);
        sgemm(embp, Wr + wo, nullptr, p_xr, NN, DD, DD);
        sgemm(embp, Wlin + wo, blin + i * DD, p_lin, NN, DD, DD);
        k_init_layer<<<ND_BLOCKS, 256>>>();
        k_edge_score<CC><<<EH_BLOCKS, 256>>>(p_xl, p_xr, att + i * HH * CC, ei);
        k_edge_exp<<<EH_BLOCKS, 256>>>(ei);
        k_edge_agg<<<EE, 256>>>(ei, p_xl);
        k_colstats<<<256, 256>>>(bconv + i * DD);
        k_finstats<<<1, 256>>>(gnw + i * DD, gnms + i * DD);
        k_fuse<<<ND_BLOCKS, 256>>>(bconv + i * DD, gnb + i * DD);
        embp = p_emb;
    }

    // final layer
    sgemm(p_emb, fWl, nullptr, p_fxl, NN, FD, DD);
    sgemm(p_emb, fWr, nullptr, p_fxr, NN, FD, DD);
    sgemm(p_emb, fWlin, fblin, p_flin, NN, OUTC, DD);
    k_init_final<<<(NN * FD + 255) / 256, 256>>>();
    k_edge_score<OUTC><<<EH_BLOCKS, 256>>>(p_fxl, p_fxr, fatt, ei);
    k_edge_exp<<<EH_BLOCKS, 256>>>(ei);
    k_edge_agg_f<<<EE, 32>>>(ei);
    k_final<<<(NN + 255) / 256, 256>>>(fbconv, out);
}

// round 3
// speedup vs baseline: 2.3789x; 2.3789x over previous
#include <cuda_runtime.h>
#include <math.h>

#define NN 50000
#define EE 800000
#define DD 256
#define HH 4
#define CC 64
#define OUTC 5
#define FD (HH*OUTC)   // 20
#define NEG 0.2f
#define GN_EPS 1e-5f
#define SM_EPS 1e-16f

// ---------------- scratch (device globals, no allocation) ----------------
__device__ float g_emb[NN*DD];
__device__ float g_xl [NN*DD];
__device__ float g_xr [NN*DD];
__device__ float g_lin[NN*DD];
__device__ float g_agg[NN*DD];
__device__ float g_score[EE*HH];
__device__ float g_m  [NN*HH];
__device__ float g_den[NN*HH];
__device__ float g_colsum[DD];
__device__ float g_colsq [DD];
__device__ float g_mshift[DD];
__device__ float g_rsig  [DD];
__device__ float g_fxl [NN*FD];
__device__ float g_fxr [NN*FD];
__device__ float g_fagg[NN*FD];
__device__ float g_flin[NN*OUTC];

static __device__ __forceinline__ void atomicMaxF(float* addr, float val) {
    int old = __float_as_int(*addr);
    while (__int_as_float(old) < val) {
        int assumed = old;
        old = atomicCAS((int*)addr, assumed, __float_as_int(val));
        if (old == assumed) break;
    }
}

// ---------------- SGEMM: C[M,Nc] = A[M,K] @ B[K,Nc] (+bias) --------------
// 128x128 tile, BK=8, 256 threads, 8x8 per thread (4+4 split), double buffer.
#define BM 128
#define BN 128
#define BK 8

static __device__ __forceinline__ float4 ldA4(const float* A, int M, int K,
                                              int row, int k) {
    if (row < M) return *(const float4*)(A + (size_t)row * K + k);
    return make_float4(0.f, 0.f, 0.f, 0.f);
}
static __device__ __forceinline__ float4 ldB4(const float* B, int Nc,
                                              int k, int col) {
    float4 v = make_float4(0.f, 0.f, 0.f, 0.f);
    const float* p = B + (size_t)k * Nc + col;
    if ((Nc & 3) == 0) {
        if (col + 3 < Nc) v = *(const float4*)p;
    } else {
        if (col + 0 < Nc) v.x = p[0];
        if (col + 1 < Nc) v.y = p[1];
        if (col + 2 < Nc) v.z = p[2];
        if (col + 3 < Nc) v.w = p[3];
    }
    return v;
}

__global__ __launch_bounds__(256, 2)
void k_sgemm(const float* __restrict__ A, const float* __restrict__ B,
             const float* __restrict__ bias, float* __restrict__ C,
             int M, int Nc, int K) {
    __shared__ float As[2][BK][BM];
    __shared__ float Bs[2][BK][BN];

    const int tid = threadIdx.x;
    const int tx = tid & 15;        // 0..15
    const int ty = tid >> 4;        // 0..15
    const int rowBase = blockIdx.y * BM;
    const int colBase = blockIdx.x * BN;

    // global load assignments
    const int aRow = tid >> 1;            // 0..127
    const int aCol = (tid & 1) * 4;       // 0 / 4
    const int bRow = tid >> 5;            // 0..7
    const int bCol = (tid & 31) * 4;      // 0..124

    float acc[8][8];
    #pragma unroll
    for (int i = 0; i < 8; ++i)
        #pragma unroll
        for (int j = 0; j < 8; ++j) acc[i][j] = 0.f;

    // prologue: tile 0
    float4 ra = ldA4(A, M, K, rowBase + aRow, 0 + aCol);
    float4 rb = ldB4(B, Nc, 0 + bRow, colBase + bCol);
    As[0][aCol + 0][aRow] = ra.x;
    As[0][aCol + 1][aRow] = ra.y;
    As[0][aCol + 2][aRow] = ra.z;
    As[0][aCol + 3][aRow] = ra.w;
    *(float4*)&Bs[0][bRow][bCol] = rb;
    __syncthreads();

    const int nt = K / BK;
    for (int t = 0; t < nt; ++t) {
        const int cur = t & 1;
        if (t + 1 < nt) {
            ra = ldA4(A, M, K, rowBase + aRow, (t + 1) * BK + aCol);
            rb = ldB4(B, Nc, (t + 1) * BK + bRow, colBase + bCol);
        }
        #pragma unroll
        for (int k = 0; k < BK; ++k) {
            float4 a0 = *(const float4*)&As[cur][k][ty * 4];
            float4 a1 = *(const float4*)&As[cur][k][64 + ty * 4];
            float4 b0 = *(const float4*)&Bs[cur][k][tx * 4];
            float4 b1 = *(const float4*)&Bs[cur][k][64 + tx * 4];
            float av[8] = {a0.x, a0.y, a0.z, a0.w, a1.x, a1.y, a1.z, a1.w};
            float bv[8] = {b0.x, b0.y, b0.z, b0.w, b1.x, b1.y, b1.z, b1.w};
            #pragma unroll
            for (int i = 0; i < 8; ++i)
                #pragma unroll
                for (int j = 0; j < 8; ++j) acc[i][j] += av[i] * bv[j];
        }
        if (t + 1 < nt) {
            const int nb = cur ^ 1;
            As[nb][aCol + 0][aRow] = ra.x;
            As[nb][aCol + 1][aRow] = ra.y;
            As[nb][aCol + 2][aRow] = ra.z;
            As[nb][aCol + 3][aRow] = ra.w;
            *(float4*)&Bs[nb][bRow][bCol] = rb;
            __syncthreads();
        }
    }

    #pragma unroll
    for (int i = 0; i < 8; ++i) {
        int r = rowBase + (i < 4 ? ty * 4 + i : 64 + ty * 4 + (i - 4));
        if (r >= M) continue;
        #pragma unroll
        for (int j = 0; j < 8; ++j) {
            int c = colBase + (j < 4 ? tx * 4 + j : 64 + tx * 4 + (j - 4));
            if (c < Nc) {
                float v = acc[i][j];
                if (bias) v += bias[c];
                C[(size_t)r * Nc + c] = v;
            }
        }
    }
}

// ---------------- init (max/den/colstats only; big arrays via memset) -----
__global__ void k_init_nm() {
    int i = blockIdx.x * blockDim.x + threadIdx.x;
    if (i < NN * HH) { g_m[i] = __int_as_float(0xff800000); g_den[i] = 0.f; }
    if (i < DD) { g_colsum[i] = 0.f; g_colsq[i] = 0.f; }
}

// ---------------- edge scoring, C=64 vectorized ----------------
__global__ void k_edge_score64(const float4* __restrict__ xl,
                               const float4* __restrict__ xr,
                               const float* __restrict__ att,
                               const int* __restrict__ ei) {
    __shared__ float4 satt[64];   // [H=4][16]
    int tid = threadIdx.x;
    if (tid < 64) satt[tid] = ((const float4*)att)[tid];
    __syncthreads();
    int idx = blockIdx.x * 256 + tid;
    if (idx >= EE * HH) return;
    int e = idx >> 2, h = idx & 3;
    int src = ei[e], dst = ei[EE + e];
    const float4* pl = xl + (size_t)src * 64 + h * 16;
    const float4* pr = xr + (size_t)dst * 64 + h * 16;
    float s = 0.f;
    #pragma unroll
    for (int g = 0; g < 16; ++g) {
        float4 a = pl[g], b = pr[g], w = satt[h * 16 + g];
        float v;
        v = a.x + b.x; v = v > 0.f ? v : NEG * v; s += w.x * v;
        v = a.y + b.y; v = v > 0.f ? v : NEG * v; s += w.y * v;
        v = a.z + b.z; v = v > 0.f ? v : NEG * v; s += w.z * v;
        v = a.w + b.w; v = v > 0.f ? v : NEG * v; s += w.w * v;
    }
    g_score[idx] = s;
    atomicMaxF(&g_m[dst * HH + h], s);
}

// final-layer scoring (C=5, scalar)
__global__ void k_edge_score_f(const float* __restrict__ xl,
                               const float* __restrict__ xr,
                               const float* __restrict__ att,
                               const int* __restrict__ ei) {
    int idx = blockIdx.x * blockDim.x + threadIdx.x;
    if (idx >= EE * HH) return;
    int e = idx >> 2, h = idx & 3;
    int src = ei[e], dst = ei[EE + e];
    const float* pl = xl + (size_t)src * FD + h * OUTC;
    const float* pr = xr + (size_t)dst * FD + h * OUTC;
    const float* pa = att + h * OUTC;
    float s = 0.f;
    #pragma unroll
    for (int c = 0; c < OUTC; ++c) {
        float v = pl[c] + pr[c];
        v = v > 0.f ? v : NEG * v;
        s += pa[c] * v;
    }
    g_score[idx] = s;
    atomicMaxF(&g_m[dst * HH + h], s);
}

__global__ void k_edge_exp(const int* __restrict__ ei) {
    int idx = blockIdx.x * blockDim.x + threadIdx.x;
    if (idx >= EE * HH) return;
    int e = idx >> 2, h = idx & 3;
    int dst = ei[EE + e];
    float a = expf(g_score[idx] - g_m[dst * HH + h]);
    g_score[idx] = a;
    atomicAdd(&g_den[dst * HH + h], a);
}

// 4 edges per 256-thread block; 64 threads/edge; float4 vector atomics.
__global__ void k_edge_agg4(const int* __restrict__ ei,
                            const float4* __restrict__ xl) {
    int sub = threadIdx.x >> 6;     // 0..3
    int t = threadIdx.x & 63;       // 0..63 -> channels t*4..t*4+3
    int e = blockIdx.x * 4 + sub;
    __shared__ float sal[4][HH];
    int src = ei[e], dst = ei[EE + e];
    if (t < HH) sal[sub][t] = g_score[e * HH + t] / (g_den[dst * HH + t] + SM_EPS);
    __syncthreads();
    float a = sal[sub][t >> 4];     // head = (t*4)/64
    float4 v = xl[(size_t)src * 64 + t];
    float* dp = &g_agg[(size_t)dst * DD + t * 4];
    asm volatile("red.global.add.v4.f32 [%0], {%1,%2,%3,%4};"
                 :: "l"(dp), "f"(a * v.x), "f"(a * v.y), "f"(a * v.z), "f"(a * v.w)
                 : "memory");
}

// final-layer aggregation: 8 edges per 256-thread block, 32 threads/edge.
__global__ void k_edge_agg_f(const int* __restrict__ ei) {
    int sub = threadIdx.x >> 5;     // 0..7
    int t = threadIdx.x & 31;
    int e = blockIdx.x * 8 + sub;
    __shared__ float sal[8][HH];
    int src = ei[e], dst = ei[EE + e];
    if (t < HH) sal[sub][t] = g_score[e * HH + t] / (g_den[dst * HH + t] + SM_EPS);
    __syncthreads();
    if (t < FD) {
        atomicAdd(&g_fagg[(size_t)dst * FD + t],
                  sal[sub][t / OUTC] * g_fxl[(size_t)src * FD + t]);
    }
}

// ---------------- GraphNorm ----------------
__global__ void k_colstats(const float* __restrict__ bconv) {
    int t = threadIdx.x;  // column 0..255
    float bc = bconv[t];
    float s = 0.f, q = 0.f;
    for (int r = blockIdx.x; r < NN; r += gridDim.x) {
        float v = g_agg[(size_t)r * DD + t] + bc;
        s += v; q += v * v;
    }
    atomicAdd(&g_colsum[t], s);
    atomicAdd(&g_colsq[t], q);
}

__global__ void k_finstats(const float* __restrict__ gnw, const float* __restrict__ gnms) {
    int t = threadIdx.x;
    float mean = g_colsum[t] * (1.f / NN);
    float ms = mean * gnms[t];
    float var = g_colsq[t] * (1.f / NN) - 2.f * ms * mean + ms * ms;
    g_mshift[t] = ms;
    g_rsig[t] = gnw[t] * rsqrtf(var + GN_EPS);
}

// normalize + skip + ELU -> g_emb (float4)
__global__ void k_fuse(const float* __restrict__ bconv, const float* __restrict__ gnb) {
    int i = blockIdx.x * blockDim.x + threadIdx.x;     // over NN*64 float4s
    if (i >= NN * (DD / 4)) return;
    int c4 = (i & 63) * 4;
    float4 v = ((const float4*)g_agg)[i];
    float4 l = ((const float4*)g_lin)[i];
    float4 r;
    float t;
    t = (v.x + bconv[c4+0] - g_mshift[c4+0]) * g_rsig[c4+0] + gnb[c4+0] + l.x;
    r.x = t > 0.f ? t : expm1f(t);
    t = (v.y + bconv[c4+1] - g_mshift[c4+1]) * g_rsig[c4+1] + gnb[c4+1] + l.y;
    r.y = t > 0.f ? t : expm1f(t);
    t = (v.z + bconv[c4+2] - g_mshift[c4+2]) * g_rsig[c4+2] + gnb[c4+2] + l.z;
    r.z = t > 0.f ? t : expm1f(t);
    t = (v.w + bconv[c4+3] - g_mshift[c4+3]) * g_rsig[c4+3] + gnb[c4+3] + l.w;
    r.w = t > 0.f ? t : expm1f(t);
    ((float4*)g_emb)[i] = r;
}

// ---------------- final combine + log_softmax ----------------
__global__ void k_final(const float* __restrict__ fbconv, float* __restrict__ out) {
    int n = blockIdx.x * blockDim.x + threadIdx.x;
    if (n >= NN) return;
    float t[OUTC];
    #pragma unroll
    for (int o = 0; o < OUTC; ++o) {
        float s = 0.f;
        #pragma unroll
        for (int h = 0; h < HH; ++h) s += g_fagg[(size_t)n * FD + h * OUTC + o];
        t[o] = 0.25f * s + fbconv[o] + g_flin[(size_t)n * OUTC + o];
    }
    float m = t[0];
    #pragma unroll
    for (int o = 1; o < OUTC; ++o) m = fmaxf(m, t[o]);
    float lse = 0.f;
    #pragma unroll
    for (int o = 0; o < OUTC; ++o) lse += expf(t[o] - m);
    lse = logf(lse);
    #pragma unroll
    for (int o = 0; o < OUTC; ++o) out[(size_t)n * OUTC + o] = t[o] - m - lse;
}

// ---------------- host ----------------
static void sgemm(const float* A, const float* B, const float* bias, float* C,
                  int M, int Nc, int K) {
    dim3 grid((Nc + BN - 1) / BN, (M + BM - 1) / BM);
    k_sgemm<<<grid, 256>>>(A, B, bias, C, M, Nc, K);
}

extern "C" void kernel_launch(void* const* d_in, const int* in_sizes, int n_in,
                              void* d_out, int out_size) {
    const float* x      = (const float*)d_in[0];
    const int*   ei     = (const int*)d_in[1];
    const float* Wl     = (const float*)d_in[2];
    const float* Wr     = (const float*)d_in[3];
    const float* att    = (const float*)d_in[4];
    const float* bconv  = (const float*)d_in[5];
    const float* Wlin   = (const float*)d_in[6];
    const float* blin   = (const float*)d_in[7];
    const float* gnw    = (const float*)d_in[8];
    const float* gnb    = (const float*)d_in[9];
    const float* gnms   = (const float*)d_in[10];
    const float* fWl    = (const float*)d_in[11];
    const float* fWr    = (const float*)d_in[12];
    const float* fatt   = (const float*)d_in[13];
    const float* fbconv = (const float*)d_in[14];
    const float* fWlin  = (const float*)d_in[15];
    const float* fblin  = (const float*)d_in[16];
    float* out = (float*)d_out;

    float *p_emb, *p_xl, *p_xr, *p_lin, *p_agg, *p_fxl, *p_fxr, *p_fagg, *p_flin;
    cudaGetSymbolAddress((void**)&p_emb,  g_emb);
    cudaGetSymbolAddress((void**)&p_xl,   g_xl);
    cudaGetSymbolAddress((void**)&p_xr,   g_xr);
    cudaGetSymbolAddress((void**)&p_lin,  g_lin);
    cudaGetSymbolAddress((void**)&p_agg,  g_agg);
    cudaGetSymbolAddress((void**)&p_fxl,  g_fxl);
    cudaGetSymbolAddress((void**)&p_fxr,  g_fxr);
    cudaGetSymbolAddress((void**)&p_fagg, g_fagg);
    cudaGetSymbolAddress((void**)&p_flin, g_flin);

    const int EH_BLOCKS = (EE * HH + 255) / 256;

    const float* embp = x;
    for (int i = 0; i < 2; ++i) {
        const size_t wo = (size_t)i * DD * DD;
        sgemm(embp, Wl + wo, nullptr, p_xl, NN, DD, DD);
        sgemm(embp, Wr + wo, nullptr, p_xr, NN, DD, DD);
        sgemm(embp, Wlin + wo, blin + i * DD, p_lin, NN, DD, DD);
        cudaMemsetAsync(p_agg, 0, (size_t)NN * DD * sizeof(float));
        k_init_nm<<<(NN * HH + 255) / 256, 256>>>();
        k_edge_score64<<<EH_BLOCKS, 256>>>((const float4*)p_xl, (const float4*)p_xr,
                                           att + i * HH * CC, ei);
        k_edge_exp<<<EH_BLOCKS, 256>>>(ei);
        k_edge_agg4<<<EE / 4, 256>>>(ei, (const float4*)p_xl);
        k_colstats<<<256, 256>>>(bconv + i * DD);
        k_finstats<<<1, 256>>>(gnw + i * DD, gnms + i * DD);
        k_fuse<<<(NN * (DD / 4) + 255) / 256, 256>>>(bconv + i * DD, gnb + i * DD);
        embp = p_emb;
    }

    // final layer
    sgemm(p_emb, fWl, nullptr, p_fxl, NN, FD, DD);
    sgemm(p_emb, fWr, nullptr, p_fxr, NN, FD, DD);
    sgemm(p_emb, fWlin, fblin, p_flin, NN, OUTC, DD);
    cudaMemsetAsync(p_fagg, 0, (size_t)NN * FD * sizeof(float));
    k_init_nm<<<(NN * HH + 255) / 256, 256>>>();
    k_edge_score_f<<<EH_BLOCKS, 256>>>(p_fxl, p_fxr, fatt, ei);
    k_edge_exp<<<EH_BLOCKS, 256>>>(ei);
    k_edge_agg_f<<<EE / 8, 256>>>(ei);
    k_final<<<(NN + 255) / 256, 256>>>(fbconv, out);
}

// round 4
// speedup vs baseline: 2.6724x; 1.1234x over previous
#include <cuda_runtime.h>
#include <math.h>

#define NN 50000
#define EE 800000
#define DD 256
#define HH 4
#define CC 64
#define OUTC 5
#define FD (HH*OUTC)   // 20
#define NEG 0.2f
#define GN_EPS 1e-5f
#define SM_EPS 1e-16f

// ---------------- scratch (device globals, no allocation) ----------------
__device__ float g_emb[NN*DD];
__device__ float g_xl [NN*DD];
__device__ float g_xr [NN*DD];
__device__ float g_lin[NN*DD];
__device__ float g_agg[NN*DD];
__device__ float g_score[EE*HH];
__device__ float g_colstat[2*DD];          // [0:DD) sum, [DD:2DD) sumsq
__device__ float g_mshift[DD];
__device__ float g_rsig  [DD];
__device__ float g_fxl [NN*FD];
__device__ float g_fxr [NN*FD];
__device__ float g_fagg[NN*FD];
__device__ float g_flin[NN*OUTC];
// CSR by destination
__device__ int g_deg[NN];
__device__ int g_off[NN+1];
__device__ int g_pos[NN];
__device__ int g_eperm[EE];

// ---------------- SGEMM: C[M,Nc] = A[M,K] @ B[K,Nc] (+bias) --------------
#define BM 128
#define BN 128
#define BK 8

static __device__ __forceinline__ float4 ldA4(const float* A, int M, int K,
                                              int row, int k) {
    if (row < M) return *(const float4*)(A + (size_t)row * K + k);
    return make_float4(0.f, 0.f, 0.f, 0.f);
}
static __device__ __forceinline__ float4 ldB4(const float* B, int Nc,
                                              int k, int col) {
    float4 v = make_float4(0.f, 0.f, 0.f, 0.f);
    const float* p = B + (size_t)k * Nc + col;
    if ((Nc & 3) == 0) {
        if (col + 3 < Nc) v = *(const float4*)p;
    } else {
        if (col + 0 < Nc) v.x = p[0];
        if (col + 1 < Nc) v.y = p[1];
        if (col + 2 < Nc) v.z = p[2];
        if (col + 3 < Nc) v.w = p[3];
    }
    return v;
}

__global__ __launch_bounds__(256, 2)
void k_sgemm(const float* __restrict__ A, const float* __restrict__ B,
             const float* __restrict__ bias, float* __restrict__ C,
             int M, int Nc, int K) {
    __shared__ float As[2][BK][BM];
    __shared__ float Bs[2][BK][BN];

    const int tid = threadIdx.x;
    const int tx = tid & 15;
    const int ty = tid >> 4;
    const int rowBase = blockIdx.y * BM;
    const int colBase = blockIdx.x * BN;

    const int aRow = tid >> 1;
    const int aCol = (tid & 1) * 4;
    const int bRow = tid >> 5;
    const int bCol = (tid & 31) * 4;

    float acc[8][8];
    #pragma unroll
    for (int i = 0; i < 8; ++i)
        #pragma unroll
        for (int j = 0; j < 8; ++j) acc[i][j] = 0.f;

    float4 ra = ldA4(A, M, K, rowBase + aRow, 0 + aCol);
    float4 rb = ldB4(B, Nc, 0 + bRow, colBase + bCol);
    As[0][aCol + 0][aRow] = ra.x;
    As[0][aCol + 1][aRow] = ra.y;
    As[0][aCol + 2][aRow] = ra.z;
    As[0][aCol + 3][aRow] = ra.w;
    *(float4*)&Bs[0][bRow][bCol] = rb;
    __syncthreads();

    const int nt = K / BK;
    for (int t = 0; t < nt; ++t) {
        const int cur = t & 1;
        if (t + 1 < nt) {
            ra = ldA4(A, M, K, rowBase + aRow, (t + 1) * BK + aCol);
            rb = ldB4(B, Nc, (t + 1) * BK + bRow, colBase + bCol);
        }
        #pragma unroll
        for (int k = 0; k < BK; ++k) {
            float4 a0 = *(const float4*)&As[cur][k][ty * 4];
            float4 a1 = *(const float4*)&As[cur][k][64 + ty * 4];
            float4 b0 = *(const float4*)&Bs[cur][k][tx * 4];
            float4 b1 = *(const float4*)&Bs[cur][k][64 + tx * 4];
            float av[8] = {a0.x, a0.y, a0.z, a0.w, a1.x, a1.y, a1.z, a1.w};
            float bv[8] = {b0.x, b0.y, b0.z, b0.w, b1.x, b1.y, b1.z, b1.w};
            #pragma unroll
            for (int i = 0; i < 8; ++i)
                #pragma unroll
                for (int j = 0; j < 8; ++j) acc[i][j] += av[i] * bv[j];
        }
        if (t + 1 < nt) {
            const int nb = cur ^ 1;
            As[nb][aCol + 0][aRow] = ra.x;
            As[nb][aCol + 1][aRow] = ra.y;
            As[nb][aCol + 2][aRow] = ra.z;
            As[nb][aCol + 3][aRow] = ra.w;
            *(float4*)&Bs[nb][bRow][bCol] = rb;
            __syncthreads();
        }
    }

    #pragma unroll
    for (int i = 0; i < 8; ++i) {
        int r = rowBase + (i < 4 ? ty * 4 + i : 64 + ty * 4 + (i - 4));
        if (r >= M) continue;
        #pragma unroll
        for (int j = 0; j < 8; ++j) {
            int c = colBase + (j < 4 ? tx * 4 + j : 64 + tx * 4 + (j - 4));
            if (c < Nc) {
                float v = acc[i][j];
                if (bias) v += bias[c];
                C[(size_t)r * Nc + c] = v;
            }
        }
    }
}

// ---------------- CSR build ----------------
__global__ void k_hist(const int* __restrict__ ei) {
    int e = blockIdx.x * blockDim.x + threadIdx.x;
    if (e < EE) atomicAdd(&g_deg[ei[EE + e]], 1);
}

__global__ void k_scan() {   // 1 block, 1024 threads
    __shared__ int wsum[32];
    const int CH = 49;       // 1024*49 >= 50000
    int t = threadIdx.x;
    int base = t * CH;
    int s = 0;
    for (int i = 0; i < CH; ++i) {
        int idx = base + i;
        if (idx < NN) s += g_deg[idx];
    }
    int lane = t & 31, wid = t >> 5;
    int v = s;
    #pragma unroll
    for (int d = 1; d < 32; d <<= 1) {
        int n = __shfl_up_sync(~0u, v, d);
        if (lane >= d) v += n;
    }
    if (lane == 31) wsum[wid] = v;
    __syncthreads();
    if (wid == 0) {
        int wv = wsum[lane];
        #pragma unroll
        for (int d = 1; d < 32; d <<= 1) {
            int n = __shfl_up_sync(~0u, wv, d);
            if (lane >= d) wv += n;
        }
        wsum[lane] = wv;
    }
    __syncthreads();
    int pre = (v - s) + (wid > 0 ? wsum[wid - 1] : 0);
    for (int i = 0; i < CH; ++i) {
        int idx = base + i;
        if (idx < NN) { g_off[idx] = pre; pre += g_deg[idx]; }
    }
    if (t == 1023) g_off[NN] = pre;
}

__global__ void k_scatter(const int* __restrict__ ei) {
    int e = blockIdx.x * blockDim.x + threadIdx.x;
    if (e >= EE) return;
    int dst = ei[EE + e];
    int p = atomicAdd(&g_pos[dst], 1);
    g_eperm[g_off[dst] + p] = e;
}

// ---------------- edge scoring (no atomics) ----------------
__global__ void k_edge_score64(const float4* __restrict__ xl,
                               const float4* __restrict__ xr,
                               const float* __restrict__ att,
                               const int* __restrict__ ei) {
    __shared__ float4 satt[64];   // [H=4][16]
    int tid = threadIdx.x;
    if (tid < 64) satt[tid] = ((const float4*)att)[tid];
    __syncthreads();
    int idx = blockIdx.x * 256 + tid;
    if (idx >= EE * HH) return;
    int e = idx >> 2, h = idx & 3;
    int src = ei[e], dst = ei[EE + e];
    const float4* pl = xl + (size_t)src * 64 + h * 16;
    const float4* pr = xr + (size_t)dst * 64 + h * 16;
    float s = 0.f;
    #pragma unroll
    for (int g = 0; g < 16; ++g) {
        float4 a = pl[g], b = pr[g], w = satt[h * 16 + g];
        float v;
        v = a.x + b.x; v = v > 0.f ? v : NEG * v; s += w.x * v;
        v = a.y + b.y; v = v > 0.f ? v : NEG * v; s += w.y * v;
        v = a.z + b.z; v = v > 0.f ? v : NEG * v; s += w.z * v;
        v = a.w + b.w; v = v > 0.f ? v : NEG * v; s += w.w * v;
    }
    g_score[idx] = s;
}

__global__ void k_edge_score_f(const float* __restrict__ xl,
                               const float* __restrict__ xr,
                               const float* __restrict__ att,
                               const int* __restrict__ ei) {
    int idx = blockIdx.x * blockDim.x + threadIdx.x;
    if (idx >= EE * HH) return;
    int e = idx >> 2, h = idx & 3;
    int src = ei[e], dst = ei[EE + e];
    const float* pl = xl + (size_t)src * FD + h * OUTC;
    const float* pr = xr + (size_t)dst * FD + h * OUTC;
    const float* pa = att + h * OUTC;
    float s = 0.f;
    #pragma unroll
    for (int c = 0; c < OUTC; ++c) {
        float v = pl[c] + pr[c];
        v = v > 0.f ? v : NEG * v;
        s += pa[c] * v;
    }
    g_score[idx] = s;
}

// ---------------- segment softmax: warp per node, in-place alpha ----------
__global__ void k_softmax_csr() {
    int w = (blockIdx.x * blockDim.x + threadIdx.x) >> 5;
    if (w >= NN) return;
    int lane = threadIdx.x & 31;
    int beg = g_off[w], end = g_off[w + 1];
    int h = lane & 3;
    int j0 = beg + (lane >> 2);

    float m = -1e30f;
    for (int j = j0; j < end; j += 8) {
        int e = g_eperm[j];
        m = fmaxf(m, g_score[e * 4 + h]);
    }
    #pragma unroll
    for (int d = 4; d < 32; d <<= 1) m = fmaxf(m, __shfl_xor_sync(~0u, m, d));

    float den = 0.f;
    for (int j = j0; j < end; j += 8) {
        int e = g_eperm[j];
        den += expf(g_score[e * 4 + h] - m);
    }
    #pragma unroll
    for (int d = 4; d < 32; d <<= 1) den += __shfl_xor_sync(~0u, den, d);
    float inv = 1.f / (den + SM_EPS);

    for (int j = j0; j < end; j += 8) {
        int e = g_eperm[j];
        g_score[e * 4 + h] = expf(g_score[e * 4 + h] - m) * inv;
    }
}

// ---------------- aggregation: gather, no atomics ----------------
// 4 nodes per 256-thread block; 64 threads per node (float4 channels).
__global__ void k_agg_csr(const int* __restrict__ ei,
                          const float4* __restrict__ xl) {
    int node = blockIdx.x * 4 + (threadIdx.x >> 6);
    int t = threadIdx.x & 63;
    int h = t >> 4;
    int beg = g_off[node], end = g_off[node + 1];
    float4 acc = make_float4(0.f, 0.f, 0.f, 0.f);
    for (int j = beg; j < end; ++j) {
        int e = g_eperm[j];
        int src = ei[e];
        float a = g_score[e * 4 + h];
        float4 v = xl[(size_t)src * 64 + t];
        acc.x += a * v.x; acc.y += a * v.y; acc.z += a * v.z; acc.w += a * v.w;
    }
    ((float4*)g_agg)[(size_t)node * 64 + t] = acc;
}

// final layer: 8 nodes per 256-thread block; 32 threads/node, 20 active.
__global__ void k_agg_csr_f(const int* __restrict__ ei) {
    int node = blockIdx.x * 8 + (threadIdx.x >> 5);
    int t = threadIdx.x & 31;
    if (t >= FD) return;
    int h = t / OUTC;
    int beg = g_off[node], end = g_off[node + 1];
    float acc = 0.f;
    for (int j = beg; j < end; ++j) {
        int e = g_eperm[j];
        int src = ei[e];
        acc += g_score[e * 4 + h] * g_fxl[(size_t)src * FD + t];
    }
    g_fagg[(size_t)node * FD + t] = acc;
}

// ---------------- GraphNorm ----------------
__global__ void k_colstats(const float* __restrict__ bconv) {
    int t = threadIdx.x;
    float bc = bconv[t];
    float s = 0.f, q = 0.f;
    for (int r = blockIdx.x; r < NN; r += gridDim.x) {
        float v = g_agg[(size_t)r * DD + t] + bc;
        s += v; q += v * v;
    }
    atomicAdd(&g_colstat[t], s);
    atomicAdd(&g_colstat[DD + t], q);
}

__global__ void k_finstats(const float* __restrict__ gnw, const float* __restrict__ gnms) {
    int t = threadIdx.x;
    float mean = g_colstat[t] * (1.f / NN);
    float ms = mean * gnms[t];
    float var = g_colstat[DD + t] * (1.f / NN) - 2.f * ms * mean + ms * ms;
    g_mshift[t] = ms;
    g_rsig[t] = gnw[t] * rsqrtf(var + GN_EPS);
}

__global__ void k_fuse(const float* __restrict__ bconv, const float* __restrict__ gnb) {
    int i = blockIdx.x * blockDim.x + threadIdx.x;
    if (i >= NN * (DD / 4)) return;
    int c4 = (i & 63) * 4;
    float4 v = ((const float4*)g_agg)[i];
    float4 l = ((const float4*)g_lin)[i];
    float4 r;
    float t;
    t = (v.x + bconv[c4+0] - g_mshift[c4+0]) * g_rsig[c4+0] + gnb[c4+0] + l.x;
    r.x = t > 0.f ? t : expm1f(t);
    t = (v.y + bconv[c4+1] - g_mshift[c4+1]) * g_rsig[c4+1] + gnb[c4+1] + l.y;
    r.y = t > 0.f ? t : expm1f(t);
    t = (v.z + bconv[c4+2] - g_mshift[c4+2]) * g_rsig[c4+2] + gnb[c4+2] + l.z;
    r.z = t > 0.f ? t : expm1f(t);
    t = (v.w + bconv[c4+3] - g_mshift[c4+3]) * g_rsig[c4+3] + gnb[c4+3] + l.w;
    r.w = t > 0.f ? t : expm1f(t);
    ((float4*)g_emb)[i] = r;
}

// ---------------- final combine + log_softmax ----------------
__global__ void k_final(const float* __restrict__ fbconv, float* __restrict__ out) {
    int n = blockIdx.x * blockDim.x + threadIdx.x;
    if (n >= NN) return;
    float t[OUTC];
    #pragma unroll
    for (int o = 0; o < OUTC; ++o) {
        float s = 0.f;
        #pragma unroll
        for (int h = 0; h < HH; ++h) s += g_fagg[(size_t)n * FD + h * OUTC + o];
        t[o] = 0.25f * s + fbconv[o] + g_flin[(size_t)n * OUTC + o];
    }
    float m = t[0];
    #pragma unroll
    for (int o = 1; o < OUTC; ++o) m = fmaxf(m, t[o]);
    float lse = 0.f;
    #pragma unroll
    for (int o = 0; o < OUTC; ++o) lse += expf(t[o] - m);
    lse = logf(lse);
    #pragma unroll
    for (int o = 0; o < OUTC; ++o) out[(size_t)n * OUTC + o] = t[o] - m - lse;
}

// ---------------- host ----------------
static void sgemm(const float* A, const float* B, const float* bias, float* C,
                  int M, int Nc, int K) {
    dim3 grid((Nc + BN - 1) / BN, (M + BM - 1) / BM);
    k_sgemm<<<grid, 256>>>(A, B, bias, C, M, Nc, K);
}

extern "C" void kernel_launch(void* const* d_in, const int* in_sizes, int n_in,
                              void* d_out, int out_size) {
    const float* x      = (const float*)d_in[0];
    const int*   ei     = (const int*)d_in[1];
    const float* Wl     = (const float*)d_in[2];
    const float* Wr     = (const float*)d_in[3];
    const float* att    = (const float*)d_in[4];
    const float* bconv  = (const float*)d_in[5];
    const float* Wlin   = (const float*)d_in[6];
    const float* blin   = (const float*)d_in[7];
    const float* gnw    = (const float*)d_in[8];
    const float* gnb    = (const float*)d_in[9];
    const float* gnms   = (const float*)d_in[10];
    const float* fWl    = (const float*)d_in[11];
    const float* fWr    = (const float*)d_in[12];
    const float* fatt   = (const float*)d_in[13];
    const float* fbconv = (const float*)d_in[14];
    const float* fWlin  = (const float*)d_in[15];
    const float* fblin  = (const float*)d_in[16];
    float* out = (float*)d_out;

    float *p_emb, *p_xl, *p_xr, *p_lin, *p_fxl, *p_fxr, *p_flin, *p_colstat;
    int *p_deg, *p_pos;
    cudaGetSymbolAddress((void**)&p_emb,  g_emb);
    cudaGetSymbolAddress((void**)&p_xl,   g_xl);
    cudaGetSymbolAddress((void**)&p_xr,   g_xr);
    cudaGetSymbolAddress((void**)&p_lin,  g_lin);
    cudaGetSymbolAddress((void**)&p_fxl,  g_fxl);
    cudaGetSymbolAddress((void**)&p_fxr,  g_fxr);
    cudaGetSymbolAddress((void**)&p_flin, g_flin);
    cudaGetSymbolAddress((void**)&p_colstat, g_colstat);
    cudaGetSymbolAddress((void**)&p_deg,  g_deg);
    cudaGetSymbolAddress((void**)&p_pos,  g_pos);

    const int EH_BLOCKS = (EE * HH + 255) / 256;
    const int E_BLOCKS  = (EE + 255) / 256;

    // ---- CSR build (once per launch) ----
    cudaMemsetAsync(p_deg, 0, NN * sizeof(int));
    cudaMemsetAsync(p_pos, 0, NN * sizeof(int));
    k_hist<<<E_BLOCKS, 256>>>(ei);
    k_scan<<<1, 1024>>>();
    k_scatter<<<E_BLOCKS, 256>>>(ei);

    const float* embp = x;
    for (int i = 0; i < 2; ++i) {
        const size_t wo = (size_t)i * DD * DD;
        sgemm(embp, Wl + wo, nullptr, p_xl, NN, DD, DD);
        sgemm(embp, Wr + wo, nullptr, p_xr, NN, DD, DD);
        sgemm(embp, Wlin + wo, blin + i * DD, p_lin, NN, DD, DD);
        k_edge_score64<<<EH_BLOCKS, 256>>>((const float4*)p_xl, (const float4*)p_xr,
                                           att + i * HH * CC, ei);
        k_softmax_csr<<<(NN + 7) / 8, 256>>>();
        k_agg_csr<<<NN / 4, 256>>>(ei, (const float4*)p_xl);
        cudaMemsetAsync(p_colstat, 0, 2 * DD * sizeof(float));
        k_colstats<<<256, 256>>>(bconv + i * DD);
        k_finstats<<<1, 256>>>(gnw + i * DD, gnms + i * DD);
        k_fuse<<<(NN * (DD / 4) + 255) / 256, 256>>>(bconv + i * DD, gnb + i * DD);
        embp = p_emb;
    }

    // final layer
    sgemm(p_emb, fWl, nullptr, p_fxl, NN, FD, DD);
    sgemm(p_emb, fWr, nullptr, p_fxr, NN, FD, DD);
    sgemm(p_emb, fWlin, fblin, p_flin, NN, OUTC, DD);
    k_edge_score_f<<<EH_BLOCKS, 256>>>(p_fxl, p_fxr, fatt, ei);
    k_softmax_csr<<<(NN + 7) / 8, 256>>>();
    k_agg_csr_f<<<NN / 8, 256>>>(ei);
    k_final<<<(NN + 255) / 256, 256>>>(fbconv, out);
}